// round 5
// baseline (speedup 1.0000x reference)
#include <cuda_runtime.h>
#include <math.h>

#define NN   50000
#define EE   800000
#define DIN  64
#define DH   128
#define DOUT 10
#define EPS  1e-8f

#define NPB  32
#define TBLK ((NN + NPB - 1) / NPB)

#define SCB  1024
#define NSB  ((NN + SCB - 1) / SCB)   // 49

#define ONB  25

typedef unsigned long long ull;

// ---------------- scratch ----------------
__device__ int   g_degi[NN];        // zero-initialized; scanC re-zeroes after use
__device__ int   g_rowptr[NN + 1];
__device__ int   g_cursor[NN];
__device__ int   g_csrsrc[EE];
__device__ float g_s[NN * DOUT];
__device__ float g_t[NN * DOUT];
__device__ int   g_bsum[64];

// ---------------- f32x2 helpers ----------------
__device__ __forceinline__ ull fma2(ull a, ull b, ull c) {
    ull d;
    asm("fma.rn.f32x2 %0, %1, %2, %3;" : "=l"(d) : "l"(a), "l"(b), "l"(c));
    return d;
}
__device__ __forceinline__ ull dup2(float v) {
    ull d;
    asm("mov.b64 %0, {%1, %1};" : "=l"(d) : "f"(v));
    return d;
}
__device__ __forceinline__ void unpack2(ull v, float& lo, float& hi) {
    asm("mov.b64 {%0, %1}, %2;" : "=f"(lo), "=f"(hi) : "l"(v));
}

// ---------------- CSR build ----------------
__global__ void count_kernel(const int4* __restrict__ dst4) {
    int t = blockIdx.x * blockDim.x + threadIdx.x;
    if (t < EE / 4) {
        int4 d = dst4[t];
        atomicAdd(&g_degi[d.x], 1);
        atomicAdd(&g_degi[d.y], 1);
        atomicAdd(&g_degi[d.z], 1);
        atomicAdd(&g_degi[d.w], 1);
    }
}

// phase A: per-block sums
__global__ void scanA_kernel() {
    __shared__ int ws[32];
    int tid = threadIdx.x;
    int i = blockIdx.x * SCB + tid;
    int v = (i < NN) ? g_degi[i] : 0;
    #pragma unroll
    for (int o = 16; o > 0; o >>= 1) v += __shfl_down_sync(0xFFFFFFFFu, v, o);
    int lane = tid & 31, wid = tid >> 5;
    if (lane == 0) ws[wid] = v;
    __syncthreads();
    if (wid == 0) {
        int t = ws[lane];
        #pragma unroll
        for (int o = 16; o > 0; o >>= 1) t += __shfl_down_sync(0xFFFFFFFFu, t, o);
        if (lane == 0) g_bsum[blockIdx.x] = t;
    }
}

// phase C: per-block scan + self-computed global offset; resets g_degi
__global__ void scanC_kernel() {
    __shared__ int wsum[32];
    __shared__ int blockoff;
    int tid = threadIdx.x;
    int lane = tid & 31, wid = tid >> 5;
    int i = blockIdx.x * SCB + tid;
    int v = (i < NN) ? g_degi[i] : 0;
    int inc = v;
    #pragma unroll
    for (int o = 1; o < 32; o <<= 1) {
        int u = __shfl_up_sync(0xFFFFFFFFu, inc, o);
        if (lane >= o) inc += u;
    }
    if (lane == 31) wsum[wid] = inc;
    __syncthreads();
    if (wid == 0) {
        int t = wsum[lane];
        #pragma unroll
        for (int o = 1; o < 32; o <<= 1) {
            int u = __shfl_up_sync(0xFFFFFFFFu, t, o);
            if (lane >= o) t += u;
        }
        wsum[lane] = t;
    }
    if (wid == 1) {
        int off = 0;
        for (int b = lane; b < blockIdx.x; b += 32) off += g_bsum[b];
        #pragma unroll
        for (int o = 16; o > 0; o >>= 1) off += __shfl_down_sync(0xFFFFFFFFu, off, o);
        if (lane == 0) blockoff = off;
    }
    __syncthreads();
    int excl = inc - v + (wid > 0 ? wsum[wid - 1] : 0) + blockoff;
    if (i < NN) {
        g_rowptr[i] = excl;
        g_cursor[i] = excl;
        g_degi[i] = 0;                       // reset for next replay
        if (i == NN - 1) g_rowptr[NN] = excl + v;
    }
}

__global__ void fill_kernel(const int4* __restrict__ src4, const int4* __restrict__ dst4) {
    int t = blockIdx.x * blockDim.x + threadIdx.x;
    if (t < EE / 4) {
        int4 s = src4[t];
        int4 d = dst4[t];
        g_csrsrc[atomicAdd(&g_cursor[d.x], 1)] = s.x;
        g_csrsrc[atomicAdd(&g_cursor[d.y], 1)] = s.y;
        g_csrsrc[atomicAdd(&g_cursor[d.z], 1)] = s.z;
        g_csrsrc[atomicAdd(&g_cursor[d.w], 1)] = s.w;
    }
}

// ---------------- fused gather + transform + layer-1 projection ----------------
// 32 nodes/block, 128 threads.
// dyn smem: sh_s[NPB*66] | sh_n[NPB*66] | shW1[128*20] | sh_h[NPB*132] | sh_rp[33]
__global__ void __launch_bounds__(128) transform_kernel(
    const float* __restrict__ x,
    const float* __restrict__ Ws0,   // (65,128)
    const float* __restrict__ Wn0,   // (65,128)
    const float* __restrict__ Ws1,   // (129,10)
    const float* __restrict__ Wn1)   // (129,10)
{
    extern __shared__ char dyn[];
    float* sh_s = (float*)dyn;
    float* sh_n = sh_s + NPB * 66;
    float* shW1 = sh_n + NPB * 66;
    float* sh_h = shW1 + 128 * 20;
    int*   sh_rp = (int*)(sh_h + NPB * 132);

    const int tid = threadIdx.x;
    const int lane = tid & 31;
    const int wid  = tid >> 5;
    const int nb  = blockIdx.x * NPB;

    // stage rowptr for this tile
    if (tid < NPB + 1) {
        int gi = nb + tid;
        sh_rp[tid] = (gi <= NN) ? g_rowptr[gi] : g_rowptr[NN];
    }

    // stage self rows + W1
    for (int idx = tid; idx < NPB * DIN; idx += 128) {
        int node = idx >> 6;
        int k    = idx & 63;
        int gn   = nb + node;
        sh_s[node * 66 + k] = (gn < NN) ? x[(size_t)gn * DIN + k] : 0.f;
    }
    if (tid < NPB) {
        int gn = nb + tid;
        sh_s[tid * 66 + DIN] = (gn < NN) ? 1.f : 0.f;
    }
    for (int idx = tid; idx < 128 * 20; idx += 128) {
        int k = idx / 20;
        int j = idx - k * 20;
        shW1[idx] = (j < 10) ? Ws1[k * DOUT + j] : Wn1[k * DOUT + (j - 10)];
    }
    __syncthreads();

    // ---- gather: warp handles 8 nodes, lane = feature pair ----
    #pragma unroll 1
    for (int i = 0; i < 8; i++) {
        int nl = wid * 8 + i;
        int gn = nb + nl;
        int beg = sh_rp[nl], end = sh_rp[nl + 1];
        if (gn >= NN) { beg = 0; end = 0; }
        float ax = 0.f, ay = 0.f, bx = 0.f, by = 0.f;
        int j = beg;
        for (; j + 4 <= end; j += 4) {
            int s0 = g_csrsrc[j], s1 = g_csrsrc[j + 1], s2 = g_csrsrc[j + 2], s3 = g_csrsrc[j + 3];
            float2 v0 = *(const float2*)(x + (size_t)s0 * DIN + lane * 2);
            float2 v1 = *(const float2*)(x + (size_t)s1 * DIN + lane * 2);
            float2 v2 = *(const float2*)(x + (size_t)s2 * DIN + lane * 2);
            float2 v3 = *(const float2*)(x + (size_t)s3 * DIN + lane * 2);
            ax += v0.x; ay += v0.y;
            bx += v1.x; by += v1.y;
            ax += v2.x; ay += v2.y;
            bx += v3.x; by += v3.y;
        }
        for (; j < end; j++) {
            int s = g_csrsrc[j];
            float2 v = *(const float2*)(x + (size_t)s * DIN + lane * 2);
            ax += v.x; ay += v.y;
        }
        float degv = (float)(end - beg);
        float inv = 1.f / fmaxf(degv, 1.f);
        float2 o; o.x = (ax + bx) * inv; o.y = (ay + by) * inv;
        *(float2*)(sh_n + nl * 66 + lane * 2) = o;
        if (lane == 0) sh_n[nl * 66 + DIN] = (degv > 0.f) ? 1.f : 0.f;
    }
    __syncthreads();

    // ---- GEMM: thread = 4 nodes x 8 cols ----
    const int a  = tid >> 4;
    const int cg = tid & 15;

    ull acc[4][2][2];
    #pragma unroll
    for (int i = 0; i < 4; i++)
        #pragma unroll
        for (int p = 0; p < 2; p++) { acc[i][p][0] = 0ull; acc[i][p][1] = 0ull; }

    const float* srow = sh_s + (a * 4) * 66;
    const float* nrow = sh_n + (a * 4) * 66;

    #pragma unroll 2
    for (int k = 0; k <= DIN; k++) {
        ulonglong2 ws0v = *(const ulonglong2*)(Ws0 + k * DH + 4 * cg);
        ulonglong2 ws1v = *(const ulonglong2*)(Ws0 + k * DH + 4 * cg + 64);
        ulonglong2 wn0v = *(const ulonglong2*)(Wn0 + k * DH + 4 * cg);
        ulonglong2 wn1v = *(const ulonglong2*)(Wn0 + k * DH + 4 * cg + 64);
        #pragma unroll
        for (int i = 0; i < 4; i++) {
            ull s2 = dup2(srow[i * 66 + k]);
            ull n2 = dup2(nrow[i * 66 + k]);
            acc[i][0][0] = fma2(s2, ws0v.x, acc[i][0][0]);
            acc[i][0][1] = fma2(s2, ws0v.y, acc[i][0][1]);
            acc[i][1][0] = fma2(s2, ws1v.x, acc[i][1][0]);
            acc[i][1][1] = fma2(s2, ws1v.y, acc[i][1][1]);
            acc[i][0][0] = fma2(n2, wn0v.x, acc[i][0][0]);
            acc[i][0][1] = fma2(n2, wn0v.y, acc[i][0][1]);
            acc[i][1][0] = fma2(n2, wn1v.x, acc[i][1][0]);
            acc[i][1][1] = fma2(n2, wn1v.y, acc[i][1][1]);
        }
    }

    // ---- norm + relu -> sh_h ----
    float lo[4][2][2], hi[4][2][2];
    float tot[4];
    #pragma unroll
    for (int i = 0; i < 4; i++) {
        float sq = 0.f;
        #pragma unroll
        for (int p = 0; p < 2; p++)
            #pragma unroll
            for (int h = 0; h < 2; h++) {
                unpack2(acc[i][p][h], lo[i][p][h], hi[i][p][h]);
                sq += lo[i][p][h] * lo[i][p][h] + hi[i][p][h] * hi[i][p][h];
            }
        tot[i] = sq;
    }
    #pragma unroll
    for (int o = 1; o < 16; o <<= 1) {
        #pragma unroll
        for (int i = 0; i < 4; i++)
            tot[i] += __shfl_xor_sync(0xFFFFFFFFu, tot[i], o);
    }
    #pragma unroll
    for (int i = 0; i < 4; i++) {
        float rinv = 1.f / (sqrtf(tot[i]) + EPS);
        int node = a * 4 + i;
        #pragma unroll
        for (int p = 0; p < 2; p++) {
            float4 hv;
            hv.x = fmaxf(lo[i][p][0] * rinv, 0.f);
            hv.y = fmaxf(hi[i][p][0] * rinv, 0.f);
            hv.z = fmaxf(lo[i][p][1] * rinv, 0.f);
            hv.w = fmaxf(hi[i][p][1] * rinv, 0.f);
            *(float4*)(sh_h + node * 132 + 4 * cg + 64 * p) = hv;
        }
    }
    __syncthreads();

    // ---- layer-1 projection ----
    {
        const int n = tid >> 2;
        const int s = tid & 3;
        ull pa[10];
        #pragma unroll
        for (int jp = 0; jp < 10; jp++) pa[jp] = 0ull;

        const float* hrow = sh_h + n * 132 + s * 32;
        #pragma unroll 4
        for (int k0 = 0; k0 < 32; k0++) {
            ull h2 = dup2(hrow[k0]);
            const ull* Wp = (const ull*)(shW1 + (s * 32 + k0) * 20);
            #pragma unroll
            for (int jp = 0; jp < 10; jp++)
                pa[jp] = fma2(h2, Wp[jp], pa[jp]);
        }
        float pj[20];
        #pragma unroll
        for (int jp = 0; jp < 10; jp++) unpack2(pa[jp], pj[2 * jp], pj[2 * jp + 1]);
        #pragma unroll
        for (int j = 0; j < 20; j++) {
            pj[j] += __shfl_xor_sync(0xFFFFFFFFu, pj[j], 1);
            pj[j] += __shfl_xor_sync(0xFFFFFFFFu, pj[j], 2);
        }
        int gn = nb + n;
        if (gn < NN) {
            #pragma unroll
            for (int j = 0; j < 20; j++) {
                if (j >= s * 5 && j < s * 5 + 5) {
                    if (j < 10)
                        g_s[gn * DOUT + j] = pj[j] + Ws1[DH * DOUT + j];
                    else
                        g_t[gn * DOUT + (j - 10)] = pj[j];
                }
            }
        }
    }
}

// ---------------- fused: layer-1 aggregation + combine + norm + log-softmax ----
__global__ void __launch_bounds__(256) output_kernel(
    const float* __restrict__ Wn1, float* __restrict__ out)
{
    __shared__ float sz[ONB * DOUT];
    int tid = threadIdx.x;
    if (tid < ONB * DOUT) {
        int nloc = tid / DOUT;
        int j = tid - nloc * DOUT;
        int node = blockIdx.x * ONB + nloc;
        if (node < NN) {
            int beg = g_rowptr[node], end = g_rowptr[node + 1];
            float acc = 0.f;
            int p = beg;
            for (; p + 2 <= end; p += 2) {
                int s0 = g_csrsrc[p], s1 = g_csrsrc[p + 1];
                acc += g_t[s0 * DOUT + j] + g_t[s1 * DOUT + j];
            }
            if (p < end) acc += g_t[g_csrsrc[p] * DOUT + j];
            float degv = (float)(end - beg);
            float inv = 1.f / fmaxf(degv, 1.f);
            float ind = (degv > 0.f) ? 1.f : 0.f;
            sz[nloc * DOUT + j] = g_s[node * DOUT + j] + acc * inv + ind * Wn1[DH * DOUT + j];
        }
    }
    __syncthreads();
    if (tid < ONB) {
        int node = blockIdx.x * ONB + tid;
        if (node < NN) {
            float v[DOUT];
            float nrm = 0.f;
            #pragma unroll
            for (int j = 0; j < DOUT; j++) { v[j] = sz[tid * DOUT + j]; nrm += v[j] * v[j]; }
            float rinv = 1.f / (sqrtf(nrm) + EPS);
            float mx = -1e30f;
            #pragma unroll
            for (int j = 0; j < DOUT; j++) { v[j] *= rinv; mx = fmaxf(mx, v[j]); }
            float se = 0.f;
            #pragma unroll
            for (int j = 0; j < DOUT; j++) se += __expf(v[j] - mx);
            float lse = mx + logf(se);
            #pragma unroll
            for (int j = 0; j < DOUT; j++) out[node * DOUT + j] = v[j] - lse;
        }
    }
}

// ---------------- launch ----------------
extern "C" void kernel_launch(void* const* d_in, const int* in_sizes, int n_in,
                              void* d_out, int out_size) {
    const float* x   = (const float*)d_in[0];
    const int*   ei  = (const int*)d_in[1];
    const float* Ws0 = (const float*)d_in[2];
    const float* Wn0 = (const float*)d_in[3];
    const float* Ws1 = (const float*)d_in[4];
    const float* Wn1 = (const float*)d_in[5];
    float* out = (float*)d_out;

    const int4* src4 = (const int4*)ei;
    const int4* dst4 = (const int4*)(ei + EE);

    const int SMEM = (NPB * 66 * 2 + 128 * 20 + NPB * 132) * 4 + 33 * 4 + 28;  // ~44.2 KB
    cudaFuncSetAttribute(transform_kernel, cudaFuncAttributeMaxDynamicSharedMemorySize, SMEM);

    count_kernel<<<(EE / 4 + 255) / 256, 256>>>(dst4);
    scanA_kernel<<<NSB, SCB>>>();
    scanC_kernel<<<NSB, SCB>>>();
    fill_kernel<<<(EE / 4 + 255) / 256, 256>>>(src4, dst4);

    transform_kernel<<<TBLK, 128, SMEM>>>(x, Ws0, Wn0, Ws1, Wn1);

    output_kernel<<<(NN + ONB - 1) / ONB, 256>>>(Wn1, out);
}

// round 6
// speedup vs baseline: 1.0883x; 1.0883x over previous
#include <cuda_runtime.h>
#include <math.h>

#define NN   50000
#define EE   800000
#define DIN  64
#define DH   128
#define DOUT 10
#define EPS  1e-8f

#define NPB  32
#define TBLK ((NN + NPB - 1) / NPB)

#define SCB  1024
#define NSB  ((NN + SCB - 1) / SCB)   // 49

#define ONB  25

typedef unsigned long long ull;

// ---------------- scratch ----------------
__device__ int   g_degi[NN];        // zero-initialized; scanC re-zeroes after use
__device__ float g_deg[NN];
__device__ int   g_rowptr[NN + 1];
__device__ int   g_cursor[NN];
__device__ int   g_csrsrc[EE];
__device__ float g_agg0[NN * DIN];  // neighbor MEAN (agg0 divides by deg)
__device__ float g_s[NN * DOUT];
__device__ float g_t[NN * DOUT];
__device__ int   g_bsum[64];

// ---------------- f32x2 helpers ----------------
__device__ __forceinline__ ull fma2(ull a, ull b, ull c) {
    ull d;
    asm("fma.rn.f32x2 %0, %1, %2, %3;" : "=l"(d) : "l"(a), "l"(b), "l"(c));
    return d;
}
__device__ __forceinline__ ull dup2(float v) {
    ull d;
    asm("mov.b64 %0, {%1, %1};" : "=l"(d) : "f"(v));
    return d;
}
__device__ __forceinline__ void unpack2(ull v, float& lo, float& hi) {
    asm("mov.b64 {%0, %1}, %2;" : "=f"(lo), "=f"(hi) : "l"(v));
}

// ---------------- CSR build ----------------
__global__ void count_kernel(const int4* __restrict__ dst4) {
    int t = blockIdx.x * blockDim.x + threadIdx.x;
    if (t < EE / 4) {
        int4 d = dst4[t];
        atomicAdd(&g_degi[d.x], 1);
        atomicAdd(&g_degi[d.y], 1);
        atomicAdd(&g_degi[d.z], 1);
        atomicAdd(&g_degi[d.w], 1);
    }
}

__global__ void scanA_kernel() {
    __shared__ int ws[32];
    int tid = threadIdx.x;
    int i = blockIdx.x * SCB + tid;
    int v = (i < NN) ? g_degi[i] : 0;
    #pragma unroll
    for (int o = 16; o > 0; o >>= 1) v += __shfl_down_sync(0xFFFFFFFFu, v, o);
    int lane = tid & 31, wid = tid >> 5;
    if (lane == 0) ws[wid] = v;
    __syncthreads();
    if (wid == 0) {
        int t = ws[lane];
        #pragma unroll
        for (int o = 16; o > 0; o >>= 1) t += __shfl_down_sync(0xFFFFFFFFu, t, o);
        if (lane == 0) g_bsum[blockIdx.x] = t;
    }
}

// per-block scan + self-computed global offset; writes rowptr/cursor/deg, resets degi
__global__ void scanC_kernel() {
    __shared__ int wsum[32];
    __shared__ int blockoff;
    int tid = threadIdx.x;
    int lane = tid & 31, wid = tid >> 5;
    int i = blockIdx.x * SCB + tid;
    int v = (i < NN) ? g_degi[i] : 0;
    int inc = v;
    #pragma unroll
    for (int o = 1; o < 32; o <<= 1) {
        int u = __shfl_up_sync(0xFFFFFFFFu, inc, o);
        if (lane >= o) inc += u;
    }
    if (lane == 31) wsum[wid] = inc;
    __syncthreads();
    if (wid == 0) {
        int t = wsum[lane];
        #pragma unroll
        for (int o = 1; o < 32; o <<= 1) {
            int u = __shfl_up_sync(0xFFFFFFFFu, t, o);
            if (lane >= o) t += u;
        }
        wsum[lane] = t;
    }
    if (wid == 1) {
        int off = 0;
        for (int b = lane; b < blockIdx.x; b += 32) off += g_bsum[b];
        #pragma unroll
        for (int o = 16; o > 0; o >>= 1) off += __shfl_down_sync(0xFFFFFFFFu, off, o);
        if (lane == 0) blockoff = off;
    }
    __syncthreads();
    int excl = inc - v + (wid > 0 ? wsum[wid - 1] : 0) + blockoff;
    if (i < NN) {
        g_rowptr[i] = excl;
        g_cursor[i] = excl;
        g_deg[i] = (float)v;
        g_degi[i] = 0;
        if (i == NN - 1) g_rowptr[NN] = excl + v;
    }
}

__global__ void fill_kernel(const int4* __restrict__ src4, const int4* __restrict__ dst4) {
    int t = blockIdx.x * blockDim.x + threadIdx.x;
    if (t < EE / 4) {
        int4 s = src4[t];
        int4 d = dst4[t];
        g_csrsrc[atomicAdd(&g_cursor[d.x], 1)] = s.x;
        g_csrsrc[atomicAdd(&g_cursor[d.y], 1)] = s.y;
        g_csrsrc[atomicAdd(&g_cursor[d.z], 1)] = s.z;
        g_csrsrc[atomicAdd(&g_cursor[d.w], 1)] = s.w;
    }
}

// ---------------- layer 0 aggregation: warp per node, half-warp float4 ----------------
// Lanes 0-15 process even-position edges, 16-31 odd-position; each lane loads a
// float4 (16B) so a 256B feature row is covered by 16 LDG.128.
__global__ void agg0_kernel(const float4* __restrict__ x4) {
    int node = blockIdx.x * (blockDim.x >> 5) + (threadIdx.x >> 5);
    if (node >= NN) return;
    int lane = threadIdx.x & 31;
    int half = lane >> 4;       // 0/1
    int hl   = lane & 15;       // float4 slot within row
    int beg = g_rowptr[node], end = g_rowptr[node + 1];

    float4 a = make_float4(0.f, 0.f, 0.f, 0.f);
    float4 b = make_float4(0.f, 0.f, 0.f, 0.f);
    int j = beg + half;
    // 4 edges per half per iteration -> 4 independent LDG.128 in flight
    for (; j + 6 < end; j += 8) {
        int s0 = g_csrsrc[j],     s1 = g_csrsrc[j + 2];
        int s2 = g_csrsrc[j + 4], s3 = g_csrsrc[j + 6];
        float4 v0 = x4[(size_t)s0 * 16 + hl];
        float4 v1 = x4[(size_t)s1 * 16 + hl];
        float4 v2 = x4[(size_t)s2 * 16 + hl];
        float4 v3 = x4[(size_t)s3 * 16 + hl];
        a.x += v0.x; a.y += v0.y; a.z += v0.z; a.w += v0.w;
        b.x += v1.x; b.y += v1.y; b.z += v1.z; b.w += v1.w;
        a.x += v2.x; a.y += v2.y; a.z += v2.z; a.w += v2.w;
        b.x += v3.x; b.y += v3.y; b.z += v3.z; b.w += v3.w;
    }
    for (; j < end; j += 2) {
        int s = g_csrsrc[j];
        float4 v = x4[(size_t)s * 16 + hl];
        a.x += v.x; a.y += v.y; a.z += v.z; a.w += v.w;
    }
    a.x += b.x; a.y += b.y; a.z += b.z; a.w += b.w;
    // combine halves
    a.x += __shfl_down_sync(0xFFFFFFFFu, a.x, 16);
    a.y += __shfl_down_sync(0xFFFFFFFFu, a.y, 16);
    a.z += __shfl_down_sync(0xFFFFFFFFu, a.z, 16);
    a.w += __shfl_down_sync(0xFFFFFFFFu, a.w, 16);
    if (lane < 16) {
        float inv = 1.f / fmaxf((float)(end - beg), 1.f);
        a.x *= inv; a.y *= inv; a.z *= inv; a.w *= inv;
        ((float4*)g_agg0)[(size_t)node * 16 + hl] = a;
    }
}

// ---------------- transform: 32 nodes/block, LDG.128 weights, FFMA2 ----------------
// dyn smem: sh_s[NPB*66] | sh_n[NPB*66] | shW1[128*20] | sh_h[NPB*132]
__global__ void __launch_bounds__(128) transform_kernel(
    const float* __restrict__ x,
    const float* __restrict__ Ws0,   // (65,128)
    const float* __restrict__ Wn0,   // (65,128)
    const float* __restrict__ Ws1,   // (129,10)
    const float* __restrict__ Wn1)   // (129,10)
{
    extern __shared__ char dyn[];
    float* sh_s = (float*)dyn;
    float* sh_n = sh_s + NPB * 66;
    float* shW1 = sh_n + NPB * 66;
    float* sh_h = shW1 + 128 * 20;

    const int tid = threadIdx.x;
    const int nb  = blockIdx.x * NPB;

    for (int idx = tid; idx < NPB * DIN; idx += 128) {
        int node = idx >> 6;
        int k    = idx & 63;
        int gn   = nb + node;
        float vs = 0.f, vn = 0.f;
        if (gn < NN) {
            vs = x[(size_t)gn * DIN + k];
            vn = g_agg0[(size_t)gn * DIN + k];
        }
        sh_s[node * 66 + k] = vs;
        sh_n[node * 66 + k] = vn;
    }
    if (tid < NPB) {
        int gn = nb + tid;
        sh_s[tid * 66 + DIN] = (gn < NN) ? 1.f : 0.f;
        sh_n[tid * 66 + DIN] = (gn < NN && g_deg[gn] > 0.f) ? 1.f : 0.f;
    }
    for (int idx = tid; idx < 128 * 20; idx += 128) {
        int k = idx / 20;
        int j = idx - k * 20;
        shW1[idx] = (j < 10) ? Ws1[k * DOUT + j] : Wn1[k * DOUT + (j - 10)];
    }
    __syncthreads();

    // ---- GEMM: thread = 4 nodes x 8 cols ----
    const int a  = tid >> 4;
    const int cg = tid & 15;

    ull acc[4][2][2];
    #pragma unroll
    for (int i = 0; i < 4; i++)
        #pragma unroll
        for (int p = 0; p < 2; p++) { acc[i][p][0] = 0ull; acc[i][p][1] = 0ull; }

    const float* srow = sh_s + (a * 4) * 66;
    const float* nrow = sh_n + (a * 4) * 66;

    #pragma unroll 2
    for (int k = 0; k <= DIN; k++) {
        ulonglong2 ws0v = *(const ulonglong2*)(Ws0 + k * DH + 4 * cg);
        ulonglong2 ws1v = *(const ulonglong2*)(Ws0 + k * DH + 4 * cg + 64);
        ulonglong2 wn0v = *(const ulonglong2*)(Wn0 + k * DH + 4 * cg);
        ulonglong2 wn1v = *(const ulonglong2*)(Wn0 + k * DH + 4 * cg + 64);
        #pragma unroll
        for (int i = 0; i < 4; i++) {
            ull s2 = dup2(srow[i * 66 + k]);
            ull n2 = dup2(nrow[i * 66 + k]);
            acc[i][0][0] = fma2(s2, ws0v.x, acc[i][0][0]);
            acc[i][0][1] = fma2(s2, ws0v.y, acc[i][0][1]);
            acc[i][1][0] = fma2(s2, ws1v.x, acc[i][1][0]);
            acc[i][1][1] = fma2(s2, ws1v.y, acc[i][1][1]);
            acc[i][0][0] = fma2(n2, wn0v.x, acc[i][0][0]);
            acc[i][0][1] = fma2(n2, wn0v.y, acc[i][0][1]);
            acc[i][1][0] = fma2(n2, wn1v.x, acc[i][1][0]);
            acc[i][1][1] = fma2(n2, wn1v.y, acc[i][1][1]);
        }
    }

    // ---- norm + relu -> sh_h ----
    float lo[4][2][2], hi[4][2][2];
    float tot[4];
    #pragma unroll
    for (int i = 0; i < 4; i++) {
        float sq = 0.f;
        #pragma unroll
        for (int p = 0; p < 2; p++)
            #pragma unroll
            for (int h = 0; h < 2; h++) {
                unpack2(acc[i][p][h], lo[i][p][h], hi[i][p][h]);
                sq += lo[i][p][h] * lo[i][p][h] + hi[i][p][h] * hi[i][p][h];
            }
        tot[i] = sq;
    }
    #pragma unroll
    for (int o = 1; o < 16; o <<= 1) {
        #pragma unroll
        for (int i = 0; i < 4; i++)
            tot[i] += __shfl_xor_sync(0xFFFFFFFFu, tot[i], o);
    }
    #pragma unroll
    for (int i = 0; i < 4; i++) {
        float rinv = 1.f / (sqrtf(tot[i]) + EPS);
        int node = a * 4 + i;
        #pragma unroll
        for (int p = 0; p < 2; p++) {
            float4 hv;
            hv.x = fmaxf(lo[i][p][0] * rinv, 0.f);
            hv.y = fmaxf(hi[i][p][0] * rinv, 0.f);
            hv.z = fmaxf(lo[i][p][1] * rinv, 0.f);
            hv.w = fmaxf(hi[i][p][1] * rinv, 0.f);
            *(float4*)(sh_h + node * 132 + 4 * cg + 64 * p) = hv;
        }
    }
    __syncthreads();

    // ---- layer-1 projection ----
    {
        const int n = tid >> 2;
        const int s = tid & 3;
        ull pa[10];
        #pragma unroll
        for (int jp = 0; jp < 10; jp++) pa[jp] = 0ull;

        const float* hrow = sh_h + n * 132 + s * 32;
        #pragma unroll 4
        for (int k0 = 0; k0 < 32; k0++) {
            ull h2 = dup2(hrow[k0]);
            const ull* Wp = (const ull*)(shW1 + (s * 32 + k0) * 20);
            #pragma unroll
            for (int jp = 0; jp < 10; jp++)
                pa[jp] = fma2(h2, Wp[jp], pa[jp]);
        }
        float pj[20];
        #pragma unroll
        for (int jp = 0; jp < 10; jp++) unpack2(pa[jp], pj[2 * jp], pj[2 * jp + 1]);
        #pragma unroll
        for (int j = 0; j < 20; j++) {
            pj[j] += __shfl_xor_sync(0xFFFFFFFFu, pj[j], 1);
            pj[j] += __shfl_xor_sync(0xFFFFFFFFu, pj[j], 2);
        }
        int gn = nb + n;
        if (gn < NN) {
            #pragma unroll
            for (int j = 0; j < 20; j++) {
                if (j >= s * 5 && j < s * 5 + 5) {
                    if (j < 10)
                        g_s[gn * DOUT + j] = pj[j] + Ws1[DH * DOUT + j];
                    else
                        g_t[gn * DOUT + (j - 10)] = pj[j];
                }
            }
        }
    }
}

// ---------------- fused: layer-1 aggregation + combine + norm + log-softmax ----
__global__ void __launch_bounds__(256) output_kernel(
    const float* __restrict__ Wn1, float* __restrict__ out)
{
    __shared__ float sz[ONB * DOUT];
    int tid = threadIdx.x;
    if (tid < ONB * DOUT) {
        int nloc = tid / DOUT;
        int j = tid - nloc * DOUT;
        int node = blockIdx.x * ONB + nloc;
        if (node < NN) {
            int beg = g_rowptr[node], end = g_rowptr[node + 1];
            float acc = 0.f;
            int p = beg;
            for (; p + 2 <= end; p += 2) {
                int s0 = g_csrsrc[p], s1 = g_csrsrc[p + 1];
                acc += g_t[s0 * DOUT + j] + g_t[s1 * DOUT + j];
            }
            if (p < end) acc += g_t[g_csrsrc[p] * DOUT + j];
            float degv = (float)(end - beg);
            float inv = 1.f / fmaxf(degv, 1.f);
            float ind = (degv > 0.f) ? 1.f : 0.f;
            sz[nloc * DOUT + j] = g_s[node * DOUT + j] + acc * inv + ind * Wn1[DH * DOUT + j];
        }
    }
    __syncthreads();
    if (tid < ONB) {
        int node = blockIdx.x * ONB + tid;
        if (node < NN) {
            float v[DOUT];
            float nrm = 0.f;
            #pragma unroll
            for (int j = 0; j < DOUT; j++) { v[j] = sz[tid * DOUT + j]; nrm += v[j] * v[j]; }
            float rinv = 1.f / (sqrtf(nrm) + EPS);
            float mx = -1e30f;
            #pragma unroll
            for (int j = 0; j < DOUT; j++) { v[j] *= rinv; mx = fmaxf(mx, v[j]); }
            float se = 0.f;
            #pragma unroll
            for (int j = 0; j < DOUT; j++) se += __expf(v[j] - mx);
            float lse = mx + logf(se);
            #pragma unroll
            for (int j = 0; j < DOUT; j++) out[node * DOUT + j] = v[j] - lse;
        }
    }
}

// ---------------- launch ----------------
extern "C" void kernel_launch(void* const* d_in, const int* in_sizes, int n_in,
                              void* d_out, int out_size) {
    const float* x   = (const float*)d_in[0];
    const int*   ei  = (const int*)d_in[1];
    const float* Ws0 = (const float*)d_in[2];
    const float* Wn0 = (const float*)d_in[3];
    const float* Ws1 = (const float*)d_in[4];
    const float* Wn1 = (const float*)d_in[5];
    float* out = (float*)d_out;

    const int4* src4 = (const int4*)ei;
    const int4* dst4 = (const int4*)(ei + EE);

    const int SMEM = (NPB * 66 * 2 + 128 * 20 + NPB * 132) * 4;  // 44032 B
    cudaFuncSetAttribute(transform_kernel, cudaFuncAttributeMaxDynamicSharedMemorySize, SMEM);

    count_kernel<<<(EE / 4 + 255) / 256, 256>>>(dst4);
    scanA_kernel<<<NSB, SCB>>>();
    scanC_kernel<<<NSB, SCB>>>();
    fill_kernel<<<(EE / 4 + 255) / 256, 256>>>(src4, dst4);

    agg0_kernel<<<(NN * 32 + 255) / 256, 256>>>((const float4*)x);
    transform_kernel<<<TBLK, 128, SMEM>>>(x, Ws0, Wn0, Ws1, Wn1);

    output_kernel<<<(NN + ONB - 1) / ONB, 256>>>(Wn1, out);
}